// round 1
// baseline (speedup 1.0000x reference)
#include <cuda_runtime.h>
#include <cuda_bf16.h>
#include <math.h>

// ---------------- problem constants ----------------
#define Bq   4
#define Cc   128
#define Hh   64
#define Ww   64
#define Ll   4096          // H*W
#define Gg   4
#define DIi  64
#define DSs  16
#define NCk  64            // number of scan chunks
#define CTk  64            // chunk length  (NCk*CTk == Ll)

// ---------------- scratch (global device arrays; no allocation) ----------------
__device__ float g_pe_t[Cc * Ll];                 // pos_embed transposed (C, L)
__device__ float g_xs[Bq * Ll * Cc];              // pre-LN activations
__device__ float g_xn[Bq * Ll * Cc];              // post-LN activations
__device__ float g_u [Gg * Bq * Ll * DIi];        // in-proj u
__device__ float g_z [Gg * Bq * Ll * DIi];        // in-proj z
__device__ float g_uc[Gg * 2 * Bq * Ll * DIi];    // conv+silu, per dir
__device__ float g_dt[Gg * 2 * Bq * Ll * DIi];    // softplus dt, per dir
__device__ float g_Bm[Gg * 2 * Bq * Ll * DSs];
__device__ float g_Cm[Gg * 2 * Bq * Ll * DSs];
__device__ float g_y [Gg * 2 * Bq * Ll * DIi];    // scan outputs (orig t order)
__device__ float g_xm[Bq * Ll * Cc];              // x_mamba
__device__ float g_carryP[32 * NCk * DIi * DSs];
__device__ float g_carryQ[32 * NCk * DIi * DSs];
__device__ float g_hstart[32 * NCk * DIi * DSs];

// ---------------- kernel 0: transpose pos_embed (L,C) -> (C,L) ----------------
__global__ void k_pet(const float* __restrict__ pe) {
    int idx = blockIdx.x * 256 + threadIdx.x;
    if (idx < Cc * Ll) {
        int c = idx >> 12;          // / 4096
        int l = idx & 4095;
        g_pe_t[idx] = pe[l * Cc + c];
    }
}

// ---------------- kernel 1: conv-pos-enc + pos_embed + LayerNorm ----------------
// block = (b,h) image row : 64 w-positions x 128 channels
__global__ void k_posln(const float* __restrict__ x, const float* __restrict__ pcw,
                        const float* __restrict__ pcb, const float* __restrict__ lng,
                        const float* __restrict__ lnb) {
    __shared__ float sv[64 * 129];
    __shared__ float sw[128 * 9];
    __shared__ float smu[64], srs[64];
    int b = blockIdx.x >> 6;
    int h = blockIdx.x & 63;
    int tid = threadIdx.x;
    for (int i = tid; i < 128 * 9; i += 256) sw[i] = pcw[i];
    __syncthreads();
    for (int idx = tid; idx < 8192; idx += 256) {
        int c = idx >> 6, w = idx & 63;
        const float* xb = x + ((size_t)(b * Cc + c)) * (Hh * Ww);
        float acc = 0.f;
#pragma unroll
        for (int kh = 0; kh < 3; kh++) {
            int hh = h + kh - 1;
            if (hh < 0 || hh >= Hh) continue;
#pragma unroll
            for (int kw = 0; kw < 3; kw++) {
                int w2 = w + kw - 1;
                if (w2 < 0 || w2 >= Ww) continue;
                acc += xb[hh * Ww + w2] * sw[c * 9 + kh * 3 + kw];
            }
        }
        float val = xb[h * Ww + w] + acc + pcb[c] + g_pe_t[c * Ll + h * Ww + w];
        sv[w * 129 + c] = val;
    }
    __syncthreads();
    if (tid < 64) {
        float s = 0.f, s2 = 0.f;
        for (int c = 0; c < 128; c++) { float v = sv[tid * 129 + c]; s += v; s2 += v * v; }
        float mu = s * (1.f / 128.f);
        float var = s2 * (1.f / 128.f) - mu * mu;
        smu[tid] = mu;
        srs[tid] = rsqrtf(var + 1e-5f);
    }
    __syncthreads();
    size_t base = ((size_t)b * Ll + h * Ww) * Cc;
    for (int idx = tid; idx < 8192; idx += 256) {
        int l = idx >> 7, c = idx & 127;
        float v = sv[l * 129 + c];
        g_xs[base + idx] = v;
        g_xn[base + idx] = (v - smu[l]) * srs[l] * lng[c] + lnb[c];
    }
}

// ---------------- kernel 2: per-group in-projection (32 -> 128) ----------------
__global__ void k_win(const float* __restrict__ Win) {
    int g = blockIdx.x >> 8;
    int tile = blockIdx.x & 255;
    __shared__ float sW[128 * 33];
    __shared__ float sX[64 * 33];
    int tid = threadIdx.x;
    for (int i = tid; i < 128 * 32; i += 256) { int o = i >> 5, k = i & 31; sW[o * 33 + k] = Win[g * 4096 + i]; }
    int row0 = tile * 64;
    for (int i = tid; i < 64 * 32; i += 256) { int r = i >> 5, k = i & 31; sX[r * 33 + k] = g_xn[(size_t)(row0 + r) * 128 + g * 32 + k]; }
    __syncthreads();
    for (int idx = tid; idx < 8192; idx += 256) {
        int r = idx >> 7, o = idx & 127;
        float acc = 0.f;
#pragma unroll
        for (int k = 0; k < 32; k++) acc += sX[r * 33 + k] * sW[o * 33 + k];
        size_t row = (size_t)row0 + r;
        if (o < 64) g_u[((size_t)g * (Bq * Ll) + row) * 64 + o] = acc;
        else        g_z[((size_t)g * (Bq * Ll) + row) * 64 + (o - 64)] = acc;
    }
}

// ---------------- kernel 3: causal dwconv + silu + xproj + dt ----------------
// block handles (g,dir,b, tile of 64 t)
__global__ void k_convproj(const float* __restrict__ conv_w, const float* __restrict__ conv_b,
                           const float* __restrict__ xproj_W, const float* __restrict__ dt_W,
                           const float* __restrict__ dt_b) {
    int bi = blockIdx.x;
    int tile = bi & 63;
    int b = (bi >> 6) & 3;
    int dir = (bi >> 8) & 1;
    int g = bi >> 9;
    int tid = threadIdx.x;
    __shared__ float su[70 * 64];      // rows t0-3 .. t0+66
    __shared__ float suc[64 * 64];
    __shared__ float sxw[34 * 65];
    __shared__ float scw[64 * 4];
    __shared__ float scb[64];
    __shared__ float sdw[64 * 2];
    __shared__ float sdb[64];
    float* sdbl = su;                  // alias (64*34 <= 70*64), used after conv phase
    int gd = g * 2 + dir;
    int t0 = tile * 64;
    for (int i = tid; i < 64 * 4; i += 256) scw[i] = conv_w[gd * 256 + i];
    for (int i = tid; i < 64; i += 256) scb[i] = conv_b[gd * 64 + i];
    for (int i = tid; i < 34 * 64; i += 256) { int o = i >> 6, k = i & 63; sxw[o * 65 + k] = xproj_W[gd * (34 * 64) + i]; }
    for (int i = tid; i < 64 * 2; i += 256) sdw[i] = dt_W[gd * 128 + i];
    for (int i = tid; i < 64; i += 256) sdb[i] = dt_b[gd * 64 + i];
    const float* ub = g_u + ((size_t)g * Bq + b) * Ll * 64;
    for (int i = tid; i < 70 * 64; i += 256) {
        int j = i >> 6, di = i & 63;
        int t = t0 - 3 + j;
        su[i] = (t >= 0 && t < Ll) ? ub[(size_t)t * 64 + di] : 0.f;
    }
    __syncthreads();
    float* ucg = g_uc + ((size_t)gd * Bq + b) * Ll * 64;
    for (int i = tid; i < 4096; i += 256) {
        int tl = i >> 6, di = i & 63;
        int j = tl + 3;
        float a;
        if (dir == 0)
            a = scw[di * 4 + 3] * su[j * 64 + di] + scw[di * 4 + 2] * su[(j - 1) * 64 + di]
              + scw[di * 4 + 1] * su[(j - 2) * 64 + di] + scw[di * 4 + 0] * su[(j - 3) * 64 + di];
        else
            a = scw[di * 4 + 3] * su[j * 64 + di] + scw[di * 4 + 2] * su[(j + 1) * 64 + di]
              + scw[di * 4 + 1] * su[(j + 2) * 64 + di] + scw[di * 4 + 0] * su[(j + 3) * 64 + di];
        a += scb[di];
        float s = a / (1.f + __expf(-a));     // silu
        suc[i] = s;
        ucg[(size_t)(t0 + tl) * 64 + di] = s;
    }
    __syncthreads();
    for (int idx = tid; idx < 64 * 34; idx += 256) {
        int tl = idx / 34, o = idx % 34;
        float acc = 0.f;
#pragma unroll
        for (int k = 0; k < 64; k++) acc += suc[tl * 64 + k] * sxw[o * 65 + k];
        sdbl[tl * 34 + o] = acc;
    }
    __syncthreads();
    float* dtg = g_dt + ((size_t)gd * Bq + b) * Ll * 64;
    for (int i = tid; i < 4096; i += 256) {
        int tl = i >> 6, di = i & 63;
        float r = sdbl[tl * 34 + 0] * sdw[di * 2 + 0] + sdbl[tl * 34 + 1] * sdw[di * 2 + 1] + sdb[di];
        float sp = (r > 15.f) ? r : log1pf(__expf(r));   // softplus
        dtg[(size_t)(t0 + tl) * 64 + di] = sp;
    }
    float* Bmg = g_Bm + ((size_t)gd * Bq + b) * Ll * 16;
    float* Cmg = g_Cm + ((size_t)gd * Bq + b) * Ll * 16;
    for (int i = tid; i < 64 * 16; i += 256) {
        int tl = i >> 4, ds = i & 15;
        Bmg[(size_t)(t0 + tl) * 16 + ds] = sdbl[tl * 34 + 2 + ds];
        Cmg[(size_t)(t0 + tl) * 16 + ds] = sdbl[tl * 34 + 18 + ds];
    }
}

// ---------------- kernels 4/6: chunked selective scan ----------------
// 4 chunk-units per block, 64 threads (thread = di) per unit; 16 states in regs.
template <int PASS>
__global__ void k_scan(const float* __restrict__ A_log, const float* __restrict__ Dskip) {
    __shared__ float sB[4][CTk * 16];
    __shared__ float sC_[4][CTk * 16];
    int tid = threadIdx.x;
    int unit = tid >> 6;
    int di = tid & 63;
    int ug = blockIdx.x * 4 + unit;
    int seq = ug >> 6;         // /NCk
    int c = ug & 63;
    int b = seq & 3;
    int dir = (seq >> 2) & 1;
    int g = seq >> 3;
    int gd = g * 2 + dir;
    size_t base_td = ((size_t)gd * Bq + b) * Ll * 64;
    size_t base_s  = ((size_t)gd * Bq + b) * Ll * 16;
    size_t base_z  = ((size_t)g * Bq + b) * Ll * 64;
    int sigma0 = c * CTk;
    for (int i = di; i < CTk * 16; i += 64) {
        int sl = i >> 4, ds = i & 15;
        int t = dir ? (Ll - 1 - (sigma0 + sl)) : (sigma0 + sl);
        sB[unit][i] = g_Bm[base_s + (size_t)t * 16 + ds];
        if (PASS == 2) sC_[unit][i] = g_Cm[base_s + (size_t)t * 16 + ds];
    }
    float Av[16];
#pragma unroll
    for (int s = 0; s < 16; s++) Av[s] = -__expf(A_log[(gd * 64 + di) * 16 + s]);
    float h[16];
    float P[16];
    size_t coff = (((size_t)seq * NCk + c) * 64 + di) * 16;
    if (PASS == 1) {
#pragma unroll
        for (int s = 0; s < 16; s++) { h[s] = 0.f; P[s] = 1.f; }
    } else {
#pragma unroll
        for (int s = 0; s < 16; s++) h[s] = g_hstart[coff + s];
    }
    float Dv = Dskip[gd * 64 + di];
    __syncthreads();
    for (int sl = 0; sl < CTk; sl++) {
        int t = dir ? (Ll - 1 - (sigma0 + sl)) : (sigma0 + sl);
        float dtv = g_dt[base_td + (size_t)t * 64 + di];
        float ucv = g_uc[base_td + (size_t)t * 64 + di];
        float dtu = dtv * ucv;
        float acc = 0.f;
#pragma unroll
        for (int s = 0; s < 16; s++) {
            float dA = __expf(dtv * Av[s]);
            h[s] = dA * h[s] + dtu * sB[unit][sl * 16 + s];
            if (PASS == 1) P[s] *= dA;
            else           acc += h[s] * sC_[unit][sl * 16 + s];
        }
        if (PASS == 2) {
            float zv = g_z[base_z + (size_t)t * 64 + di];
            float y = acc + ucv * Dv;
            y *= zv / (1.f + __expf(-zv));    // * silu(z)
            g_y[base_td + (size_t)t * 64 + di] = y;
        }
    }
    if (PASS == 1) {
#pragma unroll
        for (int s = 0; s < 16; s++) { g_carryP[coff + s] = P[s]; g_carryQ[coff + s] = h[s]; }
    }
}

// ---------------- kernel 5: compose chunk carries ----------------
__global__ void k_scanfix() {
    int idx = blockIdx.x * 256 + threadIdx.x;   // 32768 total
    int seq = idx >> 10;
    int e = idx & 1023;
    float hsv = 0.f;
    for (int c = 0; c < NCk; c++) {
        size_t off = ((size_t)seq * NCk + c) * 1024 + e;
        g_hstart[off] = hsv;
        hsv = g_carryP[off] * hsv + g_carryQ[off];
    }
}

// ---------------- kernel 7: (yf+yb) @ Wout^T -> x_mamba ----------------
__global__ void k_wout(const float* __restrict__ Wout) {
    int g = blockIdx.x >> 8;
    int tile = blockIdx.x & 255;
    __shared__ float sW[32 * 65];
    __shared__ float sY[64 * 64];
    int tid = threadIdx.x;
    for (int i = tid; i < 32 * 64; i += 256) { int o = i >> 6, k = i & 63; sW[o * 65 + k] = Wout[g * 2048 + i]; }
    int row0 = tile * 64;
    size_t basef = ((size_t)(g * 2 + 0) * Bq) * Ll * 64;
    size_t baseb = ((size_t)(g * 2 + 1) * Bq) * Ll * 64;
    for (int i = tid; i < 64 * 64; i += 256) {
        int r = i >> 6, k = i & 63;
        size_t ro = (size_t)(row0 + r) * 64 + k;
        sY[i] = g_y[basef + ro] + g_y[baseb + ro];
    }
    __syncthreads();
    for (int idx = tid; idx < 64 * 32; idx += 256) {
        int r = idx >> 5, o = idx & 31;
        float acc = 0.f;
#pragma unroll
        for (int k = 0; k < 64; k++) acc += sY[r * 64 + k] * sW[o * 65 + k];
        g_xm[(size_t)(row0 + r) * 128 + g * 32 + o] = acc;
    }
}

// ---------------- kernel 8: gate + mix + out-projection (+ transpose write) ----------------
__global__ void k_gateproj(const float* __restrict__ gW, const float* __restrict__ gb,
                           const float* __restrict__ pW, const float* __restrict__ pb,
                           float* __restrict__ out) {
    int tile = blockIdx.x;           // 512 tiles of 32 rows
    int row0 = tile * 32;
    int tid = threadIdx.x;
    __shared__ float sW[128 * 33];
    __shared__ float sIn[32 * 33];
    __shared__ float sM[32 * 129];
    float acc[16];
#pragma unroll
    for (int i = 0; i < 16; i++) acc[i] = 0.f;
    for (int ko = 0; ko < 4; ko++) {
        __syncthreads();
        for (int i = tid; i < 128 * 32; i += 256) { int o = i >> 5, k = i & 31; sW[o * 33 + k] = gW[o * 128 + ko * 32 + k]; }
        for (int i = tid; i < 32 * 32; i += 256) { int r = i >> 5, k = i & 31; sIn[r * 33 + k] = g_xn[(size_t)(row0 + r) * 128 + ko * 32 + k]; }
        __syncthreads();
#pragma unroll
        for (int j = 0; j < 16; j++) {
            int oi = tid + j * 256;
            int r = oi >> 7, o = oi & 127;
            float a = acc[j];
#pragma unroll
            for (int k = 0; k < 32; k++) a += sIn[r * 33 + k] * sW[o * 33 + k];
            acc[j] = a;
        }
    }
#pragma unroll
    for (int j = 0; j < 16; j++) {
        int oi = tid + j * 256;
        int r = oi >> 7, o = oi & 127;
        float gate = 1.f / (1.f + __expf(-(acc[j] + gb[o])));
        size_t gi = (size_t)(row0 + r) * 128 + o;
        sM[r * 129 + o] = gate * g_xm[gi] + (1.f - gate) * g_xs[gi];
        acc[j] = 0.f;
    }
    for (int ko = 0; ko < 4; ko++) {
        __syncthreads();
        for (int i = tid; i < 128 * 32; i += 256) { int o = i >> 5, k = i & 31; sW[o * 33 + k] = pW[o * 128 + ko * 32 + k]; }
        __syncthreads();
#pragma unroll
        for (int j = 0; j < 16; j++) {
            int oi = tid + j * 256;
            int r = oi >> 7, o = oi & 127;
            float a = acc[j];
#pragma unroll
            for (int k = 0; k < 32; k++) a += sM[r * 129 + ko * 32 + k] * sW[o * 33 + k];
            acc[j] = a;
        }
    }
    __syncthreads();
    float* sOut = sW;   // reuse (128*33 >= 32*129)
#pragma unroll
    for (int j = 0; j < 16; j++) {
        int oi = tid + j * 256;
        int r = oi >> 7, o = oi & 127;
        sOut[r * 129 + o] = acc[j] + pb[o];
    }
    __syncthreads();
    int b = row0 >> 12;
    int l0 = row0 & 4095;
    for (int idx = tid; idx < 4096; idx += 256) {
        int o = idx >> 5, rr = idx & 31;
        out[((size_t)(b * 128 + o)) * 4096 + l0 + rr] = sOut[rr * 129 + o];
    }
}

// ---------------- launch ----------------
extern "C" void kernel_launch(void* const* d_in, const int* in_sizes, int n_in,
                              void* d_out, int out_size) {
    const float* x    = (const float*)d_in[0];
    const float* pcw  = (const float*)d_in[1];
    const float* pcb  = (const float*)d_in[2];
    const float* pe   = (const float*)d_in[3];
    const float* lng  = (const float*)d_in[4];
    const float* lnb  = (const float*)d_in[5];
    const float* gW   = (const float*)d_in[6];
    const float* gb   = (const float*)d_in[7];
    const float* pW   = (const float*)d_in[8];
    const float* pb   = (const float*)d_in[9];
    const float* Win  = (const float*)d_in[10];
    const float* Wout = (const float*)d_in[11];
    const float* cw   = (const float*)d_in[12];
    const float* cb   = (const float*)d_in[13];
    const float* xpw  = (const float*)d_in[14];
    const float* dtw  = (const float*)d_in[15];
    const float* dtb  = (const float*)d_in[16];
    const float* alog = (const float*)d_in[17];
    const float* Dk   = (const float*)d_in[18];
    float* out = (float*)d_out;

    k_pet<<<2048, 256>>>(pe);
    k_posln<<<Bq * Hh, 256>>>(x, pcw, pcb, lng, lnb);
    k_win<<<Gg * 256, 256>>>(Win);
    k_convproj<<<Gg * 2 * Bq * (Ll / 64), 256>>>(cw, cb, xpw, dtw, dtb);
    k_scan<1><<<(32 * NCk) / 4, 256>>>(alog, Dk);
    k_scanfix<<<128, 256>>>();
    k_scan<2><<<(32 * NCk) / 4, 256>>>(alog, Dk);
    k_wout<<<Gg * 256, 256>>>(Wout);
    k_gateproj<<<(Bq * Ll) / 32, 256>>>(gW, gb, pW, pb, out);
}

// round 3
// speedup vs baseline: 1.6398x; 1.6398x over previous
#include <cuda_runtime.h>
#include <cuda_bf16.h>
#include <math.h>

// ---------------- problem constants ----------------
#define Bq   4
#define Cc   128
#define Hh   64
#define Ww   64
#define Ll   4096          // H*W
#define Gg   4
#define DIi  64
#define DSs  16
#define NCk  64            // number of scan chunks
#define CTk  64            // chunk length  (NCk*CTk == Ll)

typedef unsigned long long ull;

// ---------------- f32x2 helpers ----------------
__device__ __forceinline__ ull pk2(float a, float b) {
    ull r; asm("mov.b64 %0,{%1,%2};" : "=l"(r) : "f"(a), "f"(b)); return r;
}
__device__ __forceinline__ void upk2(ull v, float& a, float& b) {
    asm("mov.b64 {%0,%1},%2;" : "=f"(a), "=f"(b) : "l"(v));
}
__device__ __forceinline__ ull f2fma(ull a, ull b, ull c) {
    ull r; asm("fma.rn.f32x2 %0,%1,%2,%3;" : "=l"(r) : "l"(a), "l"(b), "l"(c)); return r;
}
__device__ __forceinline__ ull f2mul(ull a, ull b) {
    ull r; asm("mul.rn.f32x2 %0,%1,%2;" : "=l"(r) : "l"(a), "l"(b)); return r;
}

// ---------------- scratch ----------------
__device__ float g_xs[Bq * Ll * Cc];
__device__ float g_xn[Bq * Ll * Cc];
__device__ float g_u [Gg * Bq * Ll * DIi];
__device__ float g_z [Gg * Bq * Ll * DIi];
__device__ float g_uc[Gg * 2 * Bq * Ll * DIi];
__device__ float g_dt[Gg * 2 * Bq * Ll * DIi];
__device__ float g_Bm[Gg * 2 * Bq * Ll * DSs];
__device__ float g_Cm[Gg * 2 * Bq * Ll * DSs];
__device__ float g_y [Gg * 2 * Bq * Ll * DIi];
__device__ float g_xm[Bq * Ll * Cc];
__device__ __align__(16) float g_carryP[32 * NCk * DIi * DSs];
__device__ __align__(16) float g_carryQ[32 * NCk * DIi * DSs];
__device__ __align__(16) float g_hstart[32 * NCk * DIi * DSs];

// ---------------- kernel 1: conv-pos-enc + pos_embed + LayerNorm ----------------
__global__ void k_posln(const float* __restrict__ x, const float* __restrict__ pcw,
                        const float* __restrict__ pcb, const float* __restrict__ lng,
                        const float* __restrict__ lnb, const float* __restrict__ pe) {
    __shared__ float sv[64 * 129];
    __shared__ float sw[128 * 9];
    __shared__ float smu[64], srs[64];
    int b = blockIdx.x >> 6;
    int h = blockIdx.x & 63;
    int tid = threadIdx.x;
    for (int i = tid; i < 128 * 9; i += 256) sw[i] = pcw[i];
    __syncthreads();
    for (int idx = tid; idx < 8192; idx += 256) {
        int c = idx >> 6, w = idx & 63;
        const float* xb = x + ((size_t)(b * Cc + c)) * (Hh * Ww);
        float acc = 0.f;
#pragma unroll
        for (int kh = 0; kh < 3; kh++) {
            int hh = h + kh - 1;
            if (hh < 0 || hh >= Hh) continue;
#pragma unroll
            for (int kw = 0; kw < 3; kw++) {
                int w2 = w + kw - 1;
                if (w2 < 0 || w2 >= Ww) continue;
                acc += xb[hh * Ww + w2] * sw[c * 9 + kh * 3 + kw];
            }
        }
        sv[w * 129 + c] = xb[h * Ww + w] + acc + pcb[c];
    }
    __syncthreads();
    // pos_embed add, coalesced over channels
    for (int idx = tid; idx < 8192; idx += 256) {
        int l = idx >> 7, c = idx & 127;
        sv[l * 129 + c] += pe[((size_t)(h * 64 + l)) * 128 + c];
    }
    __syncthreads();
    if (tid < 64) {
        float s = 0.f, s2 = 0.f;
        for (int c = 0; c < 128; c++) { float v = sv[tid * 129 + c]; s += v; s2 += v * v; }
        float mu = s * (1.f / 128.f);
        float var = s2 * (1.f / 128.f) - mu * mu;
        smu[tid] = mu;
        srs[tid] = rsqrtf(var + 1e-5f);
    }
    __syncthreads();
    size_t base = ((size_t)b * Ll + h * Ww) * Cc;
    for (int idx = tid; idx < 8192; idx += 256) {
        int l = idx >> 7, c = idx & 127;
        float v = sv[l * 129 + c];
        g_xs[base + idx] = v;
        g_xn[base + idx] = (v - smu[l]) * srs[l] * lng[c] + lnb[c];
    }
}

// ---------------- kernel 2: per-group in-projection (32 -> 128), register tiled ----------------
__global__ void k_win(const float* __restrict__ Win) {
    int g = blockIdx.x >> 8;
    int tile = blockIdx.x & 255;
    int row0 = tile * 64;
    int tid = threadIdx.x;
    __shared__ float sX[32 * 68];   // [k][r]
    __shared__ float sW[32 * 132];  // [k][o]
    for (int i = tid; i < 2048; i += 256) {
        int r = i >> 5, k = i & 31;
        sX[k * 68 + r] = g_xn[(size_t)(row0 + r) * 128 + g * 32 + k];
    }
    for (int i = tid; i < 4096; i += 256) {
        int o = i >> 5, k = i & 31;
        sW[k * 132 + o] = Win[g * 4096 + i];
    }
    __syncthreads();
    int rg = tid & 15, og = tid >> 4;
    int r0 = rg * 4, o0 = og * 8;
    float acc[4][8];
#pragma unroll
    for (int i = 0; i < 4; i++)
#pragma unroll
        for (int j = 0; j < 8; j++) acc[i][j] = 0.f;
#pragma unroll 4
    for (int k = 0; k < 32; k++) {
        float4 xv = *(const float4*)&sX[k * 68 + r0];
        float4 wa = *(const float4*)&sW[k * 132 + o0];
        float4 wb = *(const float4*)&sW[k * 132 + o0 + 4];
        float xr[4] = {xv.x, xv.y, xv.z, xv.w};
        float wv[8] = {wa.x, wa.y, wa.z, wa.w, wb.x, wb.y, wb.z, wb.w};
#pragma unroll
        for (int i = 0; i < 4; i++)
#pragma unroll
            for (int j = 0; j < 8; j++) acc[i][j] += xr[i] * wv[j];
    }
#pragma unroll
    for (int i = 0; i < 4; i++) {
        size_t row = (size_t)(row0 + r0 + i);
        float4 v0 = {acc[i][0], acc[i][1], acc[i][2], acc[i][3]};
        float4 v1 = {acc[i][4], acc[i][5], acc[i][6], acc[i][7]};
        if (og < 8) {
            float* p = &g_u[((size_t)g * (Bq * Ll) + row) * 64 + o0];
            *(float4*)p = v0; *(float4*)(p + 4) = v1;
        } else {
            float* p = &g_z[((size_t)g * (Bq * Ll) + row) * 64 + (o0 - 64)];
            *(float4*)p = v0; *(float4*)(p + 4) = v1;
        }
    }
}

// ---------------- kernel 3: causal dwconv + silu + xproj + dt ----------------
// 256 threads; ALL __syncthreads() are convergent (executed unconditionally).
__global__ __launch_bounds__(256) void k_convproj(
        const float* __restrict__ conv_w, const float* __restrict__ conv_b,
        const float* __restrict__ xproj_W, const float* __restrict__ dt_W,
        const float* __restrict__ dt_b) {
    int bi = blockIdx.x;
    int tile = bi & 63;
    int b = (bi >> 6) & 3;
    int dir = (bi >> 8) & 1;
    int g = bi >> 9;
    int tid = threadIdx.x;
    int gd = g * 2 + dir;
    int t0 = tile * 64;
    __shared__ float su[64 * 73];       // [di][j]  j in [0,70)
    __shared__ float suc[64 * 68];      // [di][tl]
    __shared__ float sxw[64 * 36];      // [k][o]  o padded to 36
    __shared__ float sdbl[64 * 36];     // [tl][o]

    // xproj weights transposed to [k][o], pad cols 34,35 with zeros
    for (int i = tid; i < 2176; i += 256) {
        int o = i >> 6, di = i & 63;
        sxw[di * 36 + o] = xproj_W[gd * 2176 + i];
    }
    for (int j = tid; j < 128; j += 256) sxw[(j >> 1) * 36 + 34 + (j & 1)] = 0.f;

    // stage u into shared, transposed to [di][j]
    const float* ub = g_u + ((size_t)g * Bq + b) * Ll * 64;
    for (int i = tid; i < 70 * 64; i += 256) {
        int j = i >> 6, di = i & 63;
        int t = t0 - 3 + j;
        su[di * 73 + j] = (t >= 0 && t < Ll) ? ub[(size_t)t * 64 + di] : 0.f;
    }
    __syncthreads();

    // conv + silu: thread owns fixed di, 16 tl each
    float* ucg = g_uc + ((size_t)gd * Bq + b) * Ll * 64;
    {
        int di = tid & 63;
        int tlg = tid >> 6;
        float w0 = conv_w[gd * 256 + di * 4 + 0];
        float w1 = conv_w[gd * 256 + di * 4 + 1];
        float w2 = conv_w[gd * 256 + di * 4 + 2];
        float w3 = conv_w[gd * 256 + di * 4 + 3];
        float cb = conv_b[gd * 64 + di];
        const float* sud = &su[di * 73];
#pragma unroll 4
        for (int m = 0; m < 16; m++) {
            int tl = tlg * 16 + m;
            int j = tl + 3;
            float a;
            if (dir == 0)
                a = w3 * sud[j] + w2 * sud[j - 1] + w1 * sud[j - 2] + w0 * sud[j - 3];
            else
                a = w3 * sud[j] + w2 * sud[j + 1] + w1 * sud[j + 2] + w0 * sud[j + 3];
            a += cb;
            float s = a / (1.f + __expf(-a));
            suc[di * 68 + tl] = s;
            ucg[(size_t)(t0 + tl) * 64 + di] = s;
        }
    }
    __syncthreads();

    // xproj GEMM: 144 active lanes (16 tl-groups x 9 o-groups); inactive lanes
    // compute with clamped indices (in-bounds) and skip the store.
    {
        int tlg = tid & 15;
        int og = tid >> 4;
        bool active = (og < 9);
        int o0 = (active ? og : 8) * 4;
        int tl0 = tlg * 4;
        float acc[4][4];
#pragma unroll
        for (int i = 0; i < 4; i++)
#pragma unroll
            for (int j = 0; j < 4; j++) acc[i][j] = 0.f;
#pragma unroll 4
        for (int k = 0; k < 64; k++) {
            float4 sv4 = *(const float4*)&suc[k * 68 + tl0];
            float4 wv4 = *(const float4*)&sxw[k * 36 + o0];
            float sr[4] = {sv4.x, sv4.y, sv4.z, sv4.w};
            float wr[4] = {wv4.x, wv4.y, wv4.z, wv4.w};
#pragma unroll
            for (int i = 0; i < 4; i++)
#pragma unroll
                for (int j = 0; j < 4; j++) acc[i][j] += sr[i] * wr[j];
        }
        __syncthreads();   // convergent: all threads reach here exactly once
        if (active) {
#pragma unroll
            for (int i = 0; i < 4; i++) {
                float4 v = {acc[i][0], acc[i][1], acc[i][2], acc[i][3]};
                *(float4*)&sdbl[(tl0 + i) * 36 + o0] = v;
            }
        }
    }
    __syncthreads();

    // dt phase
    float* dtg = g_dt + ((size_t)gd * Bq + b) * Ll * 64;
    {
        int di = tid & 63;
        int tlg = tid >> 6;
        float dw0 = dt_W[gd * 128 + di * 2 + 0];
        float dw1 = dt_W[gd * 128 + di * 2 + 1];
        float db  = dt_b[gd * 64 + di];
#pragma unroll 4
        for (int m = 0; m < 16; m++) {
            int tl = tlg * 16 + m;
            float r = sdbl[tl * 36 + 0] * dw0 + sdbl[tl * 36 + 1] * dw1 + db;
            float sp = (r > 15.f) ? r : log1pf(__expf(r));
            dtg[(size_t)(t0 + tl) * 64 + di] = sp;
        }
    }
    // B/C export
    float* Bmg = g_Bm + ((size_t)gd * Bq + b) * Ll * 16;
    float* Cmg = g_Cm + ((size_t)gd * Bq + b) * Ll * 16;
    for (int i = tid; i < 1024; i += 256) {
        int tl = i >> 4, ds = i & 15;
        Bmg[(size_t)(t0 + tl) * 16 + ds] = sdbl[tl * 36 + 2 + ds];
        Cmg[(size_t)(t0 + tl) * 16 + ds] = sdbl[tl * 36 + 18 + ds];
    }
}

// ---------------- kernels 4/6: chunked selective scan (f32x2, S4D fast path) ----------------
template <int PASS>
__global__ void k_scan(const float* __restrict__ A_log, const float* __restrict__ Dskip) {
    __shared__ __align__(16) float sB[4][CTk * 16];
    __shared__ __align__(16) float sC_[4][CTk * 16];
    int tid = threadIdx.x;
    int unit = tid >> 6;
    int di = tid & 63;
    int ug = blockIdx.x * 4 + unit;
    int seq = ug >> 6;
    int c = ug & 63;
    int b = seq & 3;
    int dir = (seq >> 2) & 1;
    int g = seq >> 3;
    int gd = g * 2 + dir;
    size_t base_td = ((size_t)gd * Bq + b) * Ll * 64;
    size_t base_s  = ((size_t)gd * Bq + b) * Ll * 16;
    size_t base_z  = ((size_t)g * Bq + b) * Ll * 64;
    int sigma0 = c * CTk;
    for (int i = di; i < CTk * 16; i += 64) {
        int sl = i >> 4, ds = i & 15;
        int t = dir ? (Ll - 1 - (sigma0 + sl)) : (sigma0 + sl);
        sB[unit][i] = g_Bm[base_s + (size_t)t * 16 + ds];
        if (PASS == 2) sC_[unit][i] = g_Cm[base_s + (size_t)t * 16 + ds];
    }
    float Av[16];
    bool fast = true;
#pragma unroll
    for (int s = 0; s < 16; s++) {
        Av[s] = -__expf(A_log[(gd * 64 + di) * 16 + s]);
        if (fabsf(Av[s] + (float)(s + 1)) > 1e-3f * (float)(s + 1)) fast = false;
    }
    float Dv = Dskip[gd * 64 + di];
    size_t coff = (((size_t)seq * NCk + c) * 64 + di) * 16;
    __syncthreads();

    if (fast) {
        ull h2[8];
        if (PASS == 1) {
#pragma unroll
            for (int j = 0; j < 8; j++) h2[j] = 0ull;
        } else {
            const ull* hp = (const ull*)&g_hstart[coff];
#pragma unroll
            for (int j = 0; j < 8; j++) h2[j] = hp[j];
        }
        float sumdt = 0.f;
        for (int sl = 0; sl < CTk; sl++) {
            int t = dir ? (Ll - 1 - (sigma0 + sl)) : (sigma0 + sl);
            float dtv = g_dt[base_td + (size_t)t * 64 + di];
            float ucv = g_uc[base_td + (size_t)t * 64 + di];
            float dtu = dtv * ucv;
            float p = __expf(-dtv);
            float p2 = p * p;
            ull dA = pk2(p, p2);
            ull m  = pk2(p2, p2);
            ull du2 = pk2(dtu, dtu);
            if (PASS == 1) sumdt += dtv;
            ull acc2 = 0ull;
            const ull* bp = (const ull*)&sB[unit][sl * 16];
            const ull* cp = (const ull*)&sC_[unit][sl * 16];
#pragma unroll
            for (int j = 0; j < 8; j++) {
                h2[j] = f2fma(dA, h2[j], f2mul(du2, bp[j]));
                if (PASS == 2) acc2 = f2fma(h2[j], cp[j], acc2);
                if (j < 7) dA = f2mul(dA, m);
            }
            if (PASS == 2) {
                float alo, ahi;
                upk2(acc2, alo, ahi);
                float zv = g_z[base_z + (size_t)t * 64 + di];
                float y = alo + ahi + ucv * Dv;
                y *= zv / (1.f + __expf(-zv));
                g_y[base_td + (size_t)t * 64 + di] = y;
            }
        }
        if (PASS == 1) {
            float q = __expf(-sumdt);
            float q2 = q * q;
            ull Pp = pk2(q, q2);
            ull mq = pk2(q2, q2);
            ull* cP = (ull*)&g_carryP[coff];
            ull* cQ = (ull*)&g_carryQ[coff];
#pragma unroll
            for (int j = 0; j < 8; j++) {
                cP[j] = Pp;
                cQ[j] = h2[j];
                if (j < 7) Pp = f2mul(Pp, mq);
            }
        }
    } else {
        // general fallback (scalar)
        float h[16], P[16];
        if (PASS == 1) {
#pragma unroll
            for (int s = 0; s < 16; s++) { h[s] = 0.f; P[s] = 1.f; }
        } else {
#pragma unroll
            for (int s = 0; s < 16; s++) h[s] = g_hstart[coff + s];
        }
        for (int sl = 0; sl < CTk; sl++) {
            int t = dir ? (Ll - 1 - (sigma0 + sl)) : (sigma0 + sl);
            float dtv = g_dt[base_td + (size_t)t * 64 + di];
            float ucv = g_uc[base_td + (size_t)t * 64 + di];
            float dtu = dtv * ucv;
            float acc = 0.f;
#pragma unroll
            for (int s = 0; s < 16; s++) {
                float dA = __expf(dtv * Av[s]);
                h[s] = dA * h[s] + dtu * sB[unit][sl * 16 + s];
                if (PASS == 1) P[s] *= dA;
                else           acc += h[s] * sC_[unit][sl * 16 + s];
            }
            if (PASS == 2) {
                float zv = g_z[base_z + (size_t)t * 64 + di];
                float y = acc + ucv * Dv;
                y *= zv / (1.f + __expf(-zv));
                g_y[base_td + (size_t)t * 64 + di] = y;
            }
        }
        if (PASS == 1) {
#pragma unroll
            for (int s = 0; s < 16; s++) { g_carryP[coff + s] = P[s]; g_carryQ[coff + s] = h[s]; }
        }
    }
}

// ---------------- kernel 5: compose chunk carries (f32x2) ----------------
__global__ void k_scanfix() {
    int idx = blockIdx.x * 256 + threadIdx.x;   // 16384 = 32 seq * 512 pairs
    int seq = idx >> 9;
    int e2 = idx & 511;
    ull h = 0ull;
    const ull* P = (const ull*)g_carryP;
    const ull* Q = (const ull*)g_carryQ;
    ull* H = (ull*)g_hstart;
#pragma unroll 8
    for (int c = 0; c < NCk; c++) {
        size_t off = ((size_t)seq * NCk + c) * 512 + e2;
        H[off] = h;
        h = f2fma(P[off], h, Q[off]);
    }
}

// ---------------- kernel 7: (yf+yb) @ Wout^T -> x_mamba, register tiled ----------------
__global__ void k_wout(const float* __restrict__ Wout) {
    int g = blockIdx.x >> 8;
    int tile = blockIdx.x & 255;
    int row0 = tile * 64;
    int tid = threadIdx.x;    // 128 threads
    __shared__ float sY[64 * 68];   // [k][r]
    __shared__ float sW[64 * 36];   // [k][o]
    size_t basef = ((size_t)(g * 2 + 0) * Bq) * Ll * 64;
    size_t baseb = ((size_t)(g * 2 + 1) * Bq) * Ll * 64;
    for (int i = tid; i < 4096; i += 128) {
        int r = i >> 6, k = i & 63;
        size_t ro = (size_t)(row0 + r) * 64 + k;
        sY[k * 68 + r] = g_y[basef + ro] + g_y[baseb + ro];
    }
    for (int i = tid; i < 2048; i += 128) {
        int o = i >> 6, k = i & 63;
        sW[k * 36 + o] = Wout[g * 2048 + i];
    }
    __syncthreads();
    int rg = tid & 15, og = tid >> 4;
    int r0 = rg * 4, o0 = og * 4;
    float acc[4][4];
#pragma unroll
    for (int i = 0; i < 4; i++)
#pragma unroll
        for (int j = 0; j < 4; j++) acc[i][j] = 0.f;
#pragma unroll 4
    for (int k = 0; k < 64; k++) {
        float4 yv = *(const float4*)&sY[k * 68 + r0];
        float4 wv = *(const float4*)&sW[k * 36 + o0];
        float yr[4] = {yv.x, yv.y, yv.z, yv.w};
        float wr[4] = {wv.x, wv.y, wv.z, wv.w};
#pragma unroll
        for (int i = 0; i < 4; i++)
#pragma unroll
            for (int j = 0; j < 4; j++) acc[i][j] += yr[i] * wr[j];
    }
#pragma unroll
    for (int i = 0; i < 4; i++) {
        float4 v = {acc[i][0], acc[i][1], acc[i][2], acc[i][3]};
        *(float4*)&g_xm[(size_t)(row0 + r0 + i) * 128 + g * 32 + o0] = v;
    }
}

// ---------------- kernel 8: gate + mix + out-projection, register tiled ----------------
__global__ void k_gateproj(const float* __restrict__ gW, const float* __restrict__ gb,
                           const float* __restrict__ pW, const float* __restrict__ pb,
                           float* __restrict__ out) {
    int tile = blockIdx.x;            // 512 tiles of 32 rows
    int row0 = tile * 32;
    int tid = threadIdx.x;            // 256
    __shared__ float sIn[128 * 36];   // [k][r]  (reused as sOut [o][r pad 33])
    __shared__ float sWt[32 * 132];   // [kk][o]
    __shared__ float sM [128 * 36];   // [k][r]
    int rg = tid & 7, og = tid >> 3;
    int r0 = rg * 4, o0 = og * 4;
    float acc[4][4];
#pragma unroll
    for (int i = 0; i < 4; i++)
#pragma unroll
        for (int j = 0; j < 4; j++) acc[i][j] = 0.f;

    for (int i = tid; i < 4096; i += 256) {
        int r = i >> 7, k = i & 127;
        sIn[k * 36 + r] = g_xn[(size_t)(row0 + r) * 128 + k];
    }
    // gate GEMM
    for (int ko = 0; ko < 4; ko++) {
        __syncthreads();
        for (int i = tid; i < 4096; i += 256) {
            int o = i >> 5, kk = i & 31;
            sWt[kk * 132 + o] = gW[o * 128 + ko * 32 + kk];
        }
        __syncthreads();
#pragma unroll 4
        for (int kk = 0; kk < 32; kk++) {
            int k = ko * 32 + kk;
            float4 xv = *(const float4*)&sIn[k * 36 + r0];
            float4 wv = *(const float4*)&sWt[kk * 132 + o0];
            float xr[4] = {xv.x, xv.y, xv.z, xv.w};
            float wr[4] = {wv.x, wv.y, wv.z, wv.w};
#pragma unroll
            for (int i = 0; i < 4; i++)
#pragma unroll
                for (int j = 0; j < 4; j++) acc[i][j] += xr[i] * wr[j];
        }
    }
    // gate/mix -> sM
#pragma unroll
    for (int i = 0; i < 4; i++) {
        size_t gi = (size_t)(row0 + r0 + i) * 128 + o0;
        float4 xmv = *(const float4*)&g_xm[gi];
        float4 xsv = *(const float4*)&g_xs[gi];
        float xm[4] = {xmv.x, xmv.y, xmv.z, xmv.w};
        float xs[4] = {xsv.x, xsv.y, xsv.z, xsv.w};
#pragma unroll
        for (int j = 0; j < 4; j++) {
            float gate = 1.f / (1.f + __expf(-(acc[i][j] + gb[o0 + j])));
            sM[(o0 + j) * 36 + r0 + i] = gate * xm[j] + (1.f - gate) * xs[j];
            acc[i][j] = 0.f;
        }
    }
    // proj GEMM
    for (int ko = 0; ko < 4; ko++) {
        __syncthreads();
        for (int i = tid; i < 4096; i += 256) {
            int o = i >> 5, kk = i & 31;
            sWt[kk * 132 + o] = pW[o * 128 + ko * 32 + kk];
        }
        __syncthreads();
#pragma unroll 4
        for (int kk = 0; kk < 32; kk++) {
            int k = ko * 32 + kk;
            float4 xv = *(const float4*)&sM[k * 36 + r0];
            float4 wv = *(const float4*)&sWt[kk * 132 + o0];
            float xr[4] = {xv.x, xv.y, xv.z, xv.w};
            float wr[4] = {wv.x, wv.y, wv.z, wv.w};
#pragma unroll
            for (int i = 0; i < 4; i++)
#pragma unroll
                for (int j = 0; j < 4; j++) acc[i][j] += xr[i] * wr[j];
        }
    }
    __syncthreads();
    float* sOut = sIn;   // [o][r pad 33]
#pragma unroll
    for (int i = 0; i < 4; i++)
#pragma unroll
        for (int j = 0; j < 4; j++)
            sOut[(o0 + j) * 33 + r0 + i] = acc[i][j] + pb[o0 + j];
    __syncthreads();
    int b = row0 >> 12;
    int l0 = row0 & 4095;
    for (int idx = tid; idx < 4096; idx += 256) {
        int o = idx >> 5, rr = idx & 31;
        out[((size_t)(b * 128 + o)) * 4096 + l0 + rr] = sOut[o * 33 + rr];
    }
}

// ---------------- launch ----------------
extern "C" void kernel_launch(void* const* d_in, const int* in_sizes, int n_in,
                              void* d_out, int out_size) {
    const float* x    = (const float*)d_in[0];
    const float* pcw  = (const float*)d_in[1];
    const float* pcb  = (const float*)d_in[2];
    const float* pe   = (const float*)d_in[3];
    const float* lng  = (const float*)d_in[4];
    const float* lnb  = (const float*)d_in[5];
    const float* gW   = (const float*)d_in[6];
    const float* gb   = (const float*)d_in[7];
    const float* pW   = (const float*)d_in[8];
    const float* pb   = (const float*)d_in[9];
    const float* Win  = (const float*)d_in[10];
    const float* Wout = (const float*)d_in[11];
    const float* cw   = (const float*)d_in[12];
    const float* cb   = (const float*)d_in[13];
    const float* xpw  = (const float*)d_in[14];
    const float* dtw  = (const float*)d_in[15];
    const float* dtb  = (const float*)d_in[16];
    const float* alog = (const float*)d_in[17];
    const float* Dk   = (const float*)d_in[18];
    float* out = (float*)d_out;

    k_posln<<<Bq * Hh, 256>>>(x, pcw, pcb, lng, lnb, pe);
    k_win<<<Gg * 256, 256>>>(Win);
    k_convproj<<<Gg * 2 * Bq * (Ll / 64), 256>>>(cw, cb, xpw, dtw, dtb);
    k_scan<1><<<(32 * NCk) / 4, 256>>>(alog, Dk);
    k_scanfix<<<64, 256>>>();
    k_scan<2><<<(32 * NCk) / 4, 256>>>(alog, Dk);
    k_wout<<<Gg * 256, 128>>>(Wout);
    k_gateproj<<<(Bq * Ll) / 32, 256>>>(gW, gb, pW, pb, out);
}

// round 4
// speedup vs baseline: 1.7560x; 1.0709x over previous
#include <cuda_runtime.h>
#include <cuda_bf16.h>
#include <math.h>

// ---------------- problem constants ----------------
#define Bq   4
#define Cc   128
#define Hh   64
#define Ww   64
#define Ll   4096          // H*W
#define Gg   4
#define DIi  64
#define DSs  16
#define NCk  64            // number of scan chunks
#define CTk  64            // chunk length  (NCk*CTk == Ll)

typedef unsigned long long ull;

// ---------------- f32x2 helpers ----------------
__device__ __forceinline__ ull pk2(float a, float b) {
    ull r; asm("mov.b64 %0,{%1,%2};" : "=l"(r) : "f"(a), "f"(b)); return r;
}
__device__ __forceinline__ void upk2(ull v, float& a, float& b) {
    asm("mov.b64 {%0,%1},%2;" : "=f"(a), "=f"(b) : "l"(v));
}
__device__ __forceinline__ ull f2fma(ull a, ull b, ull c) {
    ull r; asm("fma.rn.f32x2 %0,%1,%2,%3;" : "=l"(r) : "l"(a), "l"(b), "l"(c)); return r;
}
__device__ __forceinline__ ull f2mul(ull a, ull b) {
    ull r; asm("mul.rn.f32x2 %0,%1,%2;" : "=l"(r) : "l"(a), "l"(b)); return r;
}

// ---------------- scratch ----------------
__device__ float g_xs[Bq * Ll * Cc];
__device__ float g_xn[Bq * Ll * Cc];
__device__ float g_u [Gg * Bq * Ll * DIi];
__device__ float g_z [Gg * Bq * Ll * DIi];
__device__ float2 g_du[Gg * 2 * Bq * Ll * DIi];   // (dt, uc) packed
__device__ float g_Bm[Gg * 2 * Bq * Ll * DSs];
__device__ float g_Cm[Gg * 2 * Bq * Ll * DSs];
__device__ float g_y [Gg * 2 * Bq * Ll * DIi];
__device__ float g_xm[Bq * Ll * Cc];
__device__ __align__(16) float g_carryP[32 * NCk * DIi * DSs];
__device__ __align__(16) float g_carryQ[32 * NCk * DIi * DSs];
__device__ __align__(16) float g_hstart[32 * NCk * DIi * DSs];

// ---------------- kernel 1: conv-pos-enc + pos_embed + LayerNorm ----------------
__global__ void k_posln(const float* __restrict__ x, const float* __restrict__ pcw,
                        const float* __restrict__ pcb, const float* __restrict__ lng,
                        const float* __restrict__ lnb, const float* __restrict__ pe) {
    __shared__ float sv[64 * 129];
    __shared__ float sw[128 * 9];
    __shared__ float smu[64], srs[64];
    int b = blockIdx.x >> 6;
    int h = blockIdx.x & 63;
    int tid = threadIdx.x;
    for (int i = tid; i < 128 * 9; i += 256) sw[i] = pcw[i];
    __syncthreads();
    for (int idx = tid; idx < 8192; idx += 256) {
        int c = idx >> 6, w = idx & 63;
        const float* xb = x + ((size_t)(b * Cc + c)) * (Hh * Ww);
        float acc = 0.f;
#pragma unroll
        for (int kh = 0; kh < 3; kh++) {
            int hh = h + kh - 1;
            if (hh < 0 || hh >= Hh) continue;
#pragma unroll
            for (int kw = 0; kw < 3; kw++) {
                int w2 = w + kw - 1;
                if (w2 < 0 || w2 >= Ww) continue;
                acc += xb[hh * Ww + w2] * sw[c * 9 + kh * 3 + kw];
            }
        }
        sv[w * 129 + c] = xb[h * Ww + w] + acc + pcb[c];
    }
    __syncthreads();
    for (int idx = tid; idx < 8192; idx += 256) {
        int l = idx >> 7, c = idx & 127;
        sv[l * 129 + c] += pe[((size_t)(h * 64 + l)) * 128 + c];
    }
    __syncthreads();
    if (tid < 64) {
        float s = 0.f, s2 = 0.f;
        for (int c = 0; c < 128; c++) { float v = sv[tid * 129 + c]; s += v; s2 += v * v; }
        float mu = s * (1.f / 128.f);
        float var = s2 * (1.f / 128.f) - mu * mu;
        smu[tid] = mu;
        srs[tid] = rsqrtf(var + 1e-5f);
    }
    __syncthreads();
    size_t base = ((size_t)b * Ll + h * Ww) * Cc;
    for (int idx = tid; idx < 8192; idx += 256) {
        int l = idx >> 7, c = idx & 127;
        float v = sv[l * 129 + c];
        g_xs[base + idx] = v;
        g_xn[base + idx] = (v - smu[l]) * srs[l] * lng[c] + lnb[c];
    }
}

// ---------------- kernel 2: per-group in-projection (32 -> 128), register tiled ----------------
__global__ void k_win(const float* __restrict__ Win) {
    int g = blockIdx.x >> 8;
    int tile = blockIdx.x & 255;
    int row0 = tile * 64;
    int tid = threadIdx.x;
    __shared__ float sX[32 * 68];   // [k][r]
    __shared__ float sW[32 * 132];  // [k][o]
    for (int i = tid; i < 2048; i += 256) {
        int r = i >> 5, k = i & 31;
        sX[k * 68 + r] = g_xn[(size_t)(row0 + r) * 128 + g * 32 + k];
    }
    for (int i = tid; i < 4096; i += 256) {
        int o = i >> 5, k = i & 31;
        sW[k * 132 + o] = Win[g * 4096 + i];
    }
    __syncthreads();
    int rg = tid & 15, og = tid >> 4;
    int r0 = rg * 4, o0 = og * 8;
    float acc[4][8];
#pragma unroll
    for (int i = 0; i < 4; i++)
#pragma unroll
        for (int j = 0; j < 8; j++) acc[i][j] = 0.f;
#pragma unroll 4
    for (int k = 0; k < 32; k++) {
        float4 xv = *(const float4*)&sX[k * 68 + r0];
        float4 wa = *(const float4*)&sW[k * 132 + o0];
        float4 wb = *(const float4*)&sW[k * 132 + o0 + 4];
        float xr[4] = {xv.x, xv.y, xv.z, xv.w};
        float wv[8] = {wa.x, wa.y, wa.z, wa.w, wb.x, wb.y, wb.z, wb.w};
#pragma unroll
        for (int i = 0; i < 4; i++)
#pragma unroll
            for (int j = 0; j < 8; j++) acc[i][j] += xr[i] * wv[j];
    }
#pragma unroll
    for (int i = 0; i < 4; i++) {
        size_t row = (size_t)(row0 + r0 + i);
        float4 v0 = {acc[i][0], acc[i][1], acc[i][2], acc[i][3]};
        float4 v1 = {acc[i][4], acc[i][5], acc[i][6], acc[i][7]};
        if (og < 8) {
            float* p = &g_u[((size_t)g * (Bq * Ll) + row) * 64 + o0];
            *(float4*)p = v0; *(float4*)(p + 4) = v1;
        } else {
            float* p = &g_z[((size_t)g * (Bq * Ll) + row) * 64 + (o0 - 64)];
            *(float4*)p = v0; *(float4*)(p + 4) = v1;
        }
    }
}

// ---------------- kernel 3: causal dwconv + silu + xproj + dt ----------------
__global__ __launch_bounds__(256) void k_convproj(
        const float* __restrict__ conv_w, const float* __restrict__ conv_b,
        const float* __restrict__ xproj_W, const float* __restrict__ dt_W,
        const float* __restrict__ dt_b) {
    int bi = blockIdx.x;
    int tile = bi & 63;
    int b = (bi >> 6) & 3;
    int dir = (bi >> 8) & 1;
    int g = bi >> 9;
    int tid = threadIdx.x;
    int gd = g * 2 + dir;
    int t0 = tile * 64;
    __shared__ float su[64 * 73];       // [di][j]
    __shared__ float suc[64 * 68];      // [di][tl]
    __shared__ float sxw[64 * 36];      // [k][o]
    __shared__ float sdbl[64 * 36];     // [tl][o]

    for (int i = tid; i < 2176; i += 256) {
        int o = i >> 6, di = i & 63;
        sxw[di * 36 + o] = xproj_W[gd * 2176 + i];
    }
    for (int j = tid; j < 128; j += 256) sxw[(j >> 1) * 36 + 34 + (j & 1)] = 0.f;

    const float* ub = g_u + ((size_t)g * Bq + b) * Ll * 64;
    for (int i = tid; i < 70 * 64; i += 256) {
        int j = i >> 6, di = i & 63;
        int t = t0 - 3 + j;
        su[di * 73 + j] = (t >= 0 && t < Ll) ? ub[(size_t)t * 64 + di] : 0.f;
    }
    __syncthreads();

    // conv + silu (shared only; global write deferred to the packed du store)
    {
        int di = tid & 63;
        int tlg = tid >> 6;
        float w0 = conv_w[gd * 256 + di * 4 + 0];
        float w1 = conv_w[gd * 256 + di * 4 + 1];
        float w2 = conv_w[gd * 256 + di * 4 + 2];
        float w3 = conv_w[gd * 256 + di * 4 + 3];
        float cb = conv_b[gd * 64 + di];
        const float* sud = &su[di * 73];
#pragma unroll 4
        for (int m = 0; m < 16; m++) {
            int tl = tlg * 16 + m;
            int j = tl + 3;
            float a;
            if (dir == 0)
                a = w3 * sud[j] + w2 * sud[j - 1] + w1 * sud[j - 2] + w0 * sud[j - 3];
            else
                a = w3 * sud[j] + w2 * sud[j + 1] + w1 * sud[j + 2] + w0 * sud[j + 3];
            a += cb;
            suc[di * 68 + tl] = a / (1.f + __expf(-a));
        }
    }
    __syncthreads();

    // xproj GEMM (144 active lanes; convergent barriers)
    {
        int tlg = tid & 15;
        int og = tid >> 4;
        bool active = (og < 9);
        int o0 = (active ? og : 8) * 4;
        int tl0 = tlg * 4;
        float acc[4][4];
#pragma unroll
        for (int i = 0; i < 4; i++)
#pragma unroll
            for (int j = 0; j < 4; j++) acc[i][j] = 0.f;
#pragma unroll 4
        for (int k = 0; k < 64; k++) {
            float4 sv4 = *(const float4*)&suc[k * 68 + tl0];
            float4 wv4 = *(const float4*)&sxw[k * 36 + o0];
            float sr[4] = {sv4.x, sv4.y, sv4.z, sv4.w};
            float wr[4] = {wv4.x, wv4.y, wv4.z, wv4.w};
#pragma unroll
            for (int i = 0; i < 4; i++)
#pragma unroll
                for (int j = 0; j < 4; j++) acc[i][j] += sr[i] * wr[j];
        }
        __syncthreads();
        if (active) {
#pragma unroll
            for (int i = 0; i < 4; i++) {
                float4 v = {acc[i][0], acc[i][1], acc[i][2], acc[i][3]};
                *(float4*)&sdbl[(tl0 + i) * 36 + o0] = v;
            }
        }
    }
    __syncthreads();

    // dt phase: write packed (dt, uc) float2 — coalesced
    float2* dug = g_du + ((size_t)gd * Bq + b) * Ll * 64;
    {
        int di = tid & 63;
        int tlg = tid >> 6;
        float dw0 = dt_W[gd * 128 + di * 2 + 0];
        float dw1 = dt_W[gd * 128 + di * 2 + 1];
        float db  = dt_b[gd * 64 + di];
#pragma unroll 4
        for (int m = 0; m < 16; m++) {
            int tl = tlg * 16 + m;
            float r = sdbl[tl * 36 + 0] * dw0 + sdbl[tl * 36 + 1] * dw1 + db;
            float sp = (r > 15.f) ? r : log1pf(__expf(r));
            float2 v = {sp, suc[di * 68 + tl]};
            dug[(size_t)(t0 + tl) * 64 + di] = v;
        }
    }
    float* Bmg = g_Bm + ((size_t)gd * Bq + b) * Ll * 16;
    float* Cmg = g_Cm + ((size_t)gd * Bq + b) * Ll * 16;
    for (int i = tid; i < 1024; i += 256) {
        int tl = i >> 4, ds = i & 15;
        Bmg[(size_t)(t0 + tl) * 16 + ds] = sdbl[tl * 36 + 2 + ds];
        Cmg[(size_t)(t0 + tl) * 16 + ds] = sdbl[tl * 36 + 18 + ds];
    }
}

// ---------------- kernels 4/6: chunked selective scan ----------------
// 2 units per 128-thread block; prefetched loads; log-depth dA ladder.
template <int PASS>
__global__ __launch_bounds__(128) void k_scan(const float* __restrict__ A_log,
                                              const float* __restrict__ Dskip) {
    __shared__ __align__(16) float sB[2][CTk * 16];
    __shared__ __align__(16) float sC_[2][CTk * 16];
    int tid = threadIdx.x;
    int unit = tid >> 6;
    int di = tid & 63;
    int ug = blockIdx.x * 2 + unit;
    int seq = ug >> 6;
    int c = ug & 63;
    int b = seq & 3;
    int dir = (seq >> 2) & 1;
    int g = seq >> 3;
    int gd = g * 2 + dir;
    size_t base_td = ((size_t)gd * Bq + b) * Ll * 64;
    size_t base_s  = ((size_t)gd * Bq + b) * Ll * 16;
    size_t base_z  = ((size_t)g * Bq + b) * Ll * 64;
    int sigma0 = c * CTk;
    int tstart = dir ? (Ll - 1 - sigma0) : sigma0;
    int tstep  = dir ? -1 : 1;
    for (int i = di; i < CTk * 16; i += 64) {
        int sl = i >> 4, ds = i & 15;
        int t = tstart + tstep * sl;
        sB[unit][i] = g_Bm[base_s + (size_t)t * 16 + ds];
        if (PASS == 2) sC_[unit][i] = g_Cm[base_s + (size_t)t * 16 + ds];
    }
    float Av[16];
    bool fast = true;
#pragma unroll
    for (int s = 0; s < 16; s++) {
        Av[s] = -__expf(A_log[(gd * 64 + di) * 16 + s]);
        if (fabsf(Av[s] + (float)(s + 1)) > 1e-3f * (float)(s + 1)) fast = false;
    }
    float Dv = Dskip[gd * 64 + di];
    size_t coff = (((size_t)seq * NCk + c) * 64 + di) * 16;
    __syncthreads();

    int pstep = tstep * 64;
    const float2* dup = g_du + base_td + (size_t)tstart * 64 + di;
    const float*  zp  = g_z  + base_z  + (size_t)tstart * 64 + di;
    float*        yp  = g_y  + base_td + (size_t)tstart * 64 + di;

    if (fast) {
        ull h2[8];
        if (PASS == 1) {
#pragma unroll
            for (int j = 0; j < 8; j++) h2[j] = 0ull;
        } else {
            const ull* hp = (const ull*)&g_hstart[coff];
#pragma unroll
            for (int j = 0; j < 8; j++) h2[j] = hp[j];
        }
        float sumdt = 0.f;
        float2 cur = __ldg(dup);
        float zcur = (PASS == 2) ? __ldg(zp) : 0.f;
        for (int sl = 0; sl < CTk; sl++) {
            float2 nxt = cur;
            float znxt = zcur;
            if (sl < CTk - 1) {
                dup += pstep;
                nxt = __ldg(dup);
                if (PASS == 2) { zp += pstep; znxt = __ldg(zp); }
            }
            float dtv = cur.x, ucv = cur.y;
            float dtu = dtv * ucv;
            float p = __expf(-dtv);
            float p2 = p * p;
            float p4 = p2 * p2;
            float p8 = p4 * p4;
            ull q2 = pk2(p2, p2);
            ull q4 = pk2(p4, p4);
            ull q8 = pk2(p8, p8);
            ull d0 = pk2(p, p2);
            ull d1 = f2mul(d0, q2);
            ull d2 = f2mul(d0, q4);
            ull d3 = f2mul(d1, q4);
            ull d4 = f2mul(d0, q8);
            ull d5 = f2mul(d1, q8);
            ull d6 = f2mul(d2, q8);
            ull d7 = f2mul(d3, q8);
            ull du2 = pk2(dtu, dtu);
            if (PASS == 1) sumdt += dtv;
            const ull* bp = (const ull*)&sB[unit][sl * 16];
            h2[0] = f2fma(d0, h2[0], f2mul(du2, bp[0]));
            h2[1] = f2fma(d1, h2[1], f2mul(du2, bp[1]));
            h2[2] = f2fma(d2, h2[2], f2mul(du2, bp[2]));
            h2[3] = f2fma(d3, h2[3], f2mul(du2, bp[3]));
            h2[4] = f2fma(d4, h2[4], f2mul(du2, bp[4]));
            h2[5] = f2fma(d5, h2[5], f2mul(du2, bp[5]));
            h2[6] = f2fma(d6, h2[6], f2mul(du2, bp[6]));
            h2[7] = f2fma(d7, h2[7], f2mul(du2, bp[7]));
            if (PASS == 2) {
                const ull* cp = (const ull*)&sC_[unit][sl * 16];
                ull a01 = f2mul(h2[0], cp[0]);
                ull a23 = f2mul(h2[1], cp[1]);
                ull a45 = f2mul(h2[2], cp[2]);
                ull a67 = f2mul(h2[3], cp[3]);
                a01 = f2fma(h2[4], cp[4], a01);
                a23 = f2fma(h2[5], cp[5], a23);
                a45 = f2fma(h2[6], cp[6], a45);
                a67 = f2fma(h2[7], cp[7], a67);
                a01 = pk2(__uint_as_float((unsigned)a01) + __uint_as_float((unsigned)(a01 >> 32)),
                          0.f);
                float alo, ahi, blo, bhi;
                upk2(a23, alo, ahi);
                upk2(a45, blo, bhi);
                float s1 = alo + ahi + blo + bhi;
                upk2(a67, alo, ahi);
                float acc = __uint_as_float((unsigned)a01) + s1 + alo + ahi;
                float y = acc + ucv * Dv;
                y *= zcur / (1.f + __expf(-zcur));
                *yp = y;
                yp += pstep;
            }
            cur = nxt;
            zcur = znxt;
        }
        if (PASS == 1) {
            float q = __expf(-sumdt);
            float qq2 = q * q;
            float qq4 = qq2 * qq2;
            float qq8 = qq4 * qq4;
            ull w2 = pk2(qq2, qq2);
            ull w4 = pk2(qq4, qq4);
            ull w8 = pk2(qq8, qq8);
            ull P0 = pk2(q, qq2);
            ull P1 = f2mul(P0, w2);
            ull P2 = f2mul(P0, w4);
            ull P3 = f2mul(P1, w4);
            ull* cP = (ull*)&g_carryP[coff];
            ull* cQ = (ull*)&g_carryQ[coff];
            cP[0] = P0; cP[1] = P1; cP[2] = P2; cP[3] = P3;
            cP[4] = f2mul(P0, w8); cP[5] = f2mul(P1, w8);
            cP[6] = f2mul(P2, w8); cP[7] = f2mul(P3, w8);
#pragma unroll
            for (int j = 0; j < 8; j++) cQ[j] = h2[j];
        }
    } else {
        // general fallback (scalar)
        float h[16], P[16];
        if (PASS == 1) {
#pragma unroll
            for (int s = 0; s < 16; s++) { h[s] = 0.f; P[s] = 1.f; }
        } else {
#pragma unroll
            for (int s = 0; s < 16; s++) h[s] = g_hstart[coff + s];
        }
        for (int sl = 0; sl < CTk; sl++) {
            float2 duv = dup[(size_t)(tstep * sl) * 64];
            float dtv = duv.x, ucv = duv.y;
            float dtu = dtv * ucv;
            float acc = 0.f;
#pragma unroll
            for (int s = 0; s < 16; s++) {
                float dA = __expf(dtv * Av[s]);
                h[s] = dA * h[s] + dtu * sB[unit][sl * 16 + s];
                if (PASS == 1) P[s] *= dA;
                else           acc += h[s] * sC_[unit][sl * 16 + s];
            }
            if (PASS == 2) {
                float zv = zp[(size_t)(tstep * sl) * 64];
                float y = acc + ucv * Dv;
                y *= zv / (1.f + __expf(-zv));
                yp[(size_t)(tstep * sl) * 64] = y;
            }
        }
        if (PASS == 1) {
#pragma unroll
            for (int s = 0; s < 16; s++) { g_carryP[coff + s] = P[s]; g_carryQ[coff + s] = h[s]; }
        }
    }
}

// ---------------- kernel 5: compose chunk carries (f32x2) ----------------
__global__ void k_scanfix() {
    int idx = blockIdx.x * 256 + threadIdx.x;   // 16384 = 32 seq * 512 pairs
    int seq = idx >> 9;
    int e2 = idx & 511;
    ull h = 0ull;
    const ull* P = (const ull*)g_carryP;
    const ull* Q = (const ull*)g_carryQ;
    ull* H = (ull*)g_hstart;
#pragma unroll 8
    for (int c = 0; c < NCk; c++) {
        size_t off = ((size_t)seq * NCk + c) * 512 + e2;
        H[off] = h;
        h = f2fma(P[off], h, Q[off]);
    }
}

// ---------------- kernel 7: (yf+yb) @ Wout^T -> x_mamba, register tiled ----------------
__global__ void k_wout(const float* __restrict__ Wout) {
    int g = blockIdx.x >> 8;
    int tile = blockIdx.x & 255;
    int row0 = tile * 64;
    int tid = threadIdx.x;    // 128 threads
    __shared__ float sY[64 * 68];   // [k][r]
    __shared__ float sW[64 * 36];   // [k][o]
    size_t basef = ((size_t)(g * 2 + 0) * Bq) * Ll * 64;
    size_t baseb = ((size_t)(g * 2 + 1) * Bq) * Ll * 64;
    for (int i = tid; i < 4096; i += 128) {
        int r = i >> 6, k = i & 63;
        size_t ro = (size_t)(row0 + r) * 64 + k;
        sY[k * 68 + r] = g_y[basef + ro] + g_y[baseb + ro];
    }
    for (int i = tid; i < 2048; i += 128) {
        int o = i >> 6, k = i & 63;
        sW[k * 36 + o] = Wout[g * 2048 + i];
    }
    __syncthreads();
    int rg = tid & 15, og = tid >> 4;
    int r0 = rg * 4, o0 = og * 4;
    float acc[4][4];
#pragma unroll
    for (int i = 0; i < 4; i++)
#pragma unroll
        for (int j = 0; j < 4; j++) acc[i][j] = 0.f;
#pragma unroll 4
    for (int k = 0; k < 64; k++) {
        float4 yv = *(const float4*)&sY[k * 68 + r0];
        float4 wv = *(const float4*)&sW[k * 36 + o0];
        float yr[4] = {yv.x, yv.y, yv.z, yv.w};
        float wr[4] = {wv.x, wv.y, wv.z, wv.w};
#pragma unroll
        for (int i = 0; i < 4; i++)
#pragma unroll
            for (int j = 0; j < 4; j++) acc[i][j] += yr[i] * wr[j];
    }
#pragma unroll
    for (int i = 0; i < 4; i++) {
        float4 v = {acc[i][0], acc[i][1], acc[i][2], acc[i][3]};
        *(float4*)&g_xm[(size_t)(row0 + r0 + i) * 128 + g * 32 + o0] = v;
    }
}

// ---------------- kernel 8: gate + mix + out-projection, register tiled ----------------
__global__ void k_gateproj(const float* __restrict__ gW, const float* __restrict__ gb,
                           const float* __restrict__ pW, const float* __restrict__ pb,
                           float* __restrict__ out) {
    int tile = blockIdx.x;            // 512 tiles of 32 rows
    int row0 = tile * 32;
    int tid = threadIdx.x;            // 256
    __shared__ float sIn[128 * 36];   // [k][r]  (reused as sOut [o][r pad 33])
    __shared__ float sWt[32 * 132];   // [kk][o]
    __shared__ float sM [128 * 36];   // [k][r]
    int rg = tid & 7, og = tid >> 3;
    int r0 = rg * 4, o0 = og * 4;
    float acc[4][4];
#pragma unroll
    for (int i = 0; i < 4; i++)
#pragma unroll
        for (int j = 0; j < 4; j++) acc[i][j] = 0.f;

    for (int i = tid; i < 4096; i += 256) {
        int r = i >> 7, k = i & 127;
        sIn[k * 36 + r] = g_xn[(size_t)(row0 + r) * 128 + k];
    }
    for (int ko = 0; ko < 4; ko++) {
        __syncthreads();
        for (int i = tid; i < 4096; i += 256) {
            int o = i >> 5, kk = i & 31;
            sWt[kk * 132 + o] = gW[o * 128 + ko * 32 + kk];
        }
        __syncthreads();
#pragma unroll 4
        for (int kk = 0; kk < 32; kk++) {
            int k = ko * 32 + kk;
            float4 xv = *(const float4*)&sIn[k * 36 + r0];
            float4 wv = *(const float4*)&sWt[kk * 132 + o0];
            float xr[4] = {xv.x, xv.y, xv.z, xv.w};
            float wr[4] = {wv.x, wv.y, wv.z, wv.w};
#pragma unroll
            for (int i = 0; i < 4; i++)
#pragma unroll
                for (int j = 0; j < 4; j++) acc[i][j] += xr[i] * wr[j];
        }
    }
#pragma unroll
    for (int i = 0; i < 4; i++) {
        size_t gi = (size_t)(row0 + r0 + i) * 128 + o0;
        float4 xmv = *(const float4*)&g_xm[gi];
        float4 xsv = *(const float4*)&g_xs[gi];
        float xm[4] = {xmv.x, xmv.y, xmv.z, xmv.w};
        float xs[4] = {xsv.x, xsv.y, xsv.z, xsv.w};
#pragma unroll
        for (int j = 0; j < 4; j++) {
            float gate = 1.f / (1.f + __expf(-(acc[i][j] + gb[o0 + j])));
            sM[(o0 + j) * 36 + r0 + i] = gate * xm[j] + (1.f - gate) * xs[j];
            acc[i][j] = 0.f;
        }
    }
    for (int ko = 0; ko < 4; ko++) {
        __syncthreads();
        for (int i = tid; i < 4096; i += 256) {
            int o = i >> 5, kk = i & 31;
            sWt[kk * 132 + o] = pW[o * 128 + ko * 32 + kk];
        }
        __syncthreads();
#pragma unroll 4
        for (int kk = 0; kk < 32; kk++) {
            int k = ko * 32 + kk;
            float4 xv = *(const float4*)&sM[k * 36 + r0];
            float4 wv = *(const float4*)&sWt[kk * 132 + o0];
            float xr[4] = {xv.x, xv.y, xv.z, xv.w};
            float wr[4] = {wv.x, wv.y, wv.z, wv.w};
#pragma unroll
            for (int i = 0; i < 4; i++)
#pragma unroll
                for (int j = 0; j < 4; j++) acc[i][j] += xr[i] * wr[j];
        }
    }
    __syncthreads();
    float* sOut = sIn;   // [o][r pad 33]
#pragma unroll
    for (int i = 0; i < 4; i++)
#pragma unroll
        for (int j = 0; j < 4; j++)
            sOut[(o0 + j) * 33 + r0 + i] = acc[i][j] + pb[o0 + j];
    __syncthreads();
    int b = row0 >> 12;
    int l0 = row0 & 4095;
    for (int idx = tid; idx < 4096; idx += 256) {
        int o = idx >> 5, rr = idx & 31;
        out[((size_t)(b * 128 + o)) * 4096 + l0 + rr] = sOut[o * 33 + rr];
    }
}

// ---------------- launch ----------------
extern "C" void kernel_launch(void* const* d_in, const int* in_sizes, int n_in,
                              void* d_out, int out_size) {
    const float* x    = (const float*)d_in[0];
    const float* pcw  = (const float*)d_in[1];
    const float* pcb  = (const float*)d_in[2];
    const float* pe   = (const float*)d_in[3];
    const float* lng  = (const float*)d_in[4];
    const float* lnb  = (const float*)d_in[5];
    const float* gW   = (const float*)d_in[6];
    const float* gb   = (const float*)d_in[7];
    const float* pW   = (const float*)d_in[8];
    const float* pb   = (const float*)d_in[9];
    const float* Win  = (const float*)d_in[10];
    const float* Wout = (const float*)d_in[11];
    const float* cw   = (const float*)d_in[12];
    const float* cb   = (const float*)d_in[13];
    const float* xpw  = (const float*)d_in[14];
    const float* dtw  = (const float*)d_in[15];
    const float* dtb  = (const float*)d_in[16];
    const float* alog = (const float*)d_in[17];
    const float* Dk   = (const float*)d_in[18];
    float* out = (float*)d_out;

    k_posln<<<Bq * Hh, 256>>>(x, pcw, pcb, lng, lnb, pe);
    k_win<<<Gg * 256, 256>>>(Win);
    k_convproj<<<Gg * 2 * Bq * (Ll / 64), 256>>>(cw, cb, xpw, dtw, dtb);
    k_scan<1><<<(32 * NCk) / 2, 128>>>(alog, Dk);
    k_scanfix<<<64, 256>>>();
    k_scan<2><<<(32 * NCk) / 2, 128>>>(alog, Dk);
    k_wout<<<Gg * 256, 128>>>(Wout);
    k_gateproj<<<(Bq * Ll) / 32, 256>>>(gW, gb, pW, pb, out);
}